// round 7
// baseline (speedup 1.0000x reference)
#include <cuda_runtime.h>
#include <cuda_bf16.h>
#include <math.h>
#include <stdint.h>

#define Bq 65536

// ---------------- device workspaces (sanctioned __device__ scratch) --------
__device__ __align__(16) unsigned char g_wb[24u * 262144u];   // 6 MB: BT hi/lo bf16
__device__ float g_z[12ull * Bq * 256ull];                    // z vectors fp32

// ---------------- SMEM layout (bytes) ----------------
#define BIAS_OFF 0
#define BST_OFF 136192
#define SCR_OFF 203776
#define SM_BYTES 212480
#define BPART 16896          // 32*528
#define ASTRIDE 528          // bytes per activation row (264 bf16)

__constant__ int c_AH[2] = {1024, 68608};
__constant__ int c_AL[2] = {34816, 102400};

// ---------------- helpers ----------------
__device__ __forceinline__ uint32_t smem_u32(const void* p) {
    uint32_t a;
    asm("{ .reg .u64 t; cvta.to.shared.u64 t, %1; cvt.u32.u64 %0, t; }" : "=r"(a) : "l"(p));
    return a;
}

#define LDSM4(r, addr) \
    asm volatile("ldmatrix.sync.aligned.m8n8.x4.shared.b16 {%0,%1,%2,%3}, [%4];" \
        : "=r"((r)[0]), "=r"((r)[1]), "=r"((r)[2]), "=r"((r)[3]) : "r"(addr))

#define MMA(acc, a, bb0, bb1) \
    asm volatile("mma.sync.aligned.m16n8k16.row.col.f32.bf16.bf16.f32 " \
        "{%0,%1,%2,%3},{%4,%5,%6,%7},{%8,%9},{%0,%1,%2,%3};" \
        : "+f"((acc)[0]), "+f"((acc)[1]), "+f"((acc)[2]), "+f"((acc)[3]) \
        : "r"((a)[0]), "r"((a)[1]), "r"((a)[2]), "r"((a)[3]), "r"(bb0), "r"(bb1))

__device__ __forceinline__ void cpa16(uint32_t dst, const void* src) {
    asm volatile("cp.async.cg.shared.global [%0], [%1], 16;" :: "r"(dst), "l"(src));
}
#define CP_COMMIT() asm volatile("cp.async.commit_group;" ::: "memory")
#define CP_WAIT0()  asm volatile("cp.async.wait_group 0;" ::: "memory")

__device__ __forceinline__ uint32_t pack_hi_lo(float a, float b, uint32_t* lo) {
    __nv_bfloat16 ha = __float2bfloat16(a), hb = __float2bfloat16(b);
    float ra = a - __bfloat162float(ha), rb = b - __bfloat162float(hb);
    __nv_bfloat162 hh = __halves2bfloat162(ha, hb);
    __nv_bfloat162 ll = __halves2bfloat162(__float2bfloat16(ra), __float2bfloat16(rb));
    *lo = *(uint32_t*)&ll;
    return *(uint32_t*)&hh;
}

__device__ __forceinline__ float gelu_f(float v) {
    return 0.5f * v * (1.0f + erff(v * 0.70710678118654752f));
}

// ---------------- prep: weights -> BT hi/lo bf16 blobs ----------------
__global__ void prep_kernel(const float* __restrict__ Tw1, const float* __restrict__ Tw2,
                            const float* __restrict__ Ew1, const float* __restrict__ Ew2) {
    int mat = blockIdx.x >> 3, sub = blockIdx.x & 7;
    const float* src = (mat < 11) ? Tw1 + (size_t)mat * 65536
                     : (mat < 22) ? Tw2 + (size_t)(mat - 11) * 65536
                     : (mat == 22) ? Ew1 : Ew2;
    unsigned char* baseH = g_wb + (size_t)mat * 262144u;
    for (int i = 0; i < 32; ++i) {
        int idx = sub * 8192 + i * 256 + threadIdx.x;
        int k = idx >> 8, n = idx & 255;
        float wv = src[idx];
        __nv_bfloat16 h = __float2bfloat16(wv);
        float r = wv - __bfloat162float(h);
        __nv_bfloat16 l = __float2bfloat16(r);
        size_t off = (size_t)n * 512 + (size_t)k * 2;
        *(unsigned short*)(baseH + off) = *(unsigned short*)&h;
        *(unsigned short*)(baseH + 131072u + off) = *(unsigned short*)&l;
    }
}

// ---------------- main fused MLP kernel ----------------
extern __shared__ unsigned char smem[];

__device__ __forceinline__ void issueB(uint32_t sb, int tid, int mat, int c, int stage) {
    const unsigned char* srcbase = g_wb + (size_t)mat * 262144u;
    uint32_t dstbase = sb + BST_OFF + stage * (2 * BPART);
#pragma unroll
    for (int i = 0; i < 8; ++i) {
        int g = tid + 256 * i;           // 0..2047
        int part = g >> 10;              // hi / lo
        int rem = g & 1023;
        int rw = rem >> 5;               // row within chunk 0..31
        int u = rem & 31;                // 16B unit within 512B row
        uint32_t dst = dstbase + part * BPART + rw * ASTRIDE + u * 16;
        const unsigned char* s = srcbase + (size_t)part * 131072u
                               + (size_t)(c * 32 + rw) * 512 + (size_t)u * 16;
        cpa16(dst, s);
    }
    CP_COMMIT();
}

__device__ __forceinline__ void do_layer(
    uint32_t sb, int tid, int cur, int mat, int nextMat,
    const float* __restrict__ biasPtr, bool do_gelu, bool toA,
    int slot, int b0)
{
    float* bias_s = (float*)(smem + BIAS_OFF);
    bias_s[tid] = biasPtr[tid];

    const int w = tid >> 5, lane = tid & 31;
    const int kh = w >> 2;              // K half (0: k<128, 1: k>=128)
    const int wm = (w >> 1) & 1;        // 32-row slice
    const int wn = w & 1;               // 16-col slice
    const int gid = lane >> 2, tig = lane & 3;

    const int rowA0 = wm * 32 + (lane & 15);
    const int koffA = (lane >> 4) * 16 + kh * 256;     // bytes
    const int rowB = wn * 16 + ((lane >> 4) << 3) + (lane & 7);
    const int koffB = ((lane >> 3) & 1) * 16 + kh * 256;

    const uint32_t aHb = sb + c_AH[cur] + rowA0 * ASTRIDE + koffA;
    const uint32_t aLb = sb + c_AL[cur] + rowA0 * ASTRIDE + koffA;
    float* scr = (float*)(smem + SCR_OFF);

    // ---- A-stationary: preload this warp's full A slice into registers ----
    uint32_t ah[2][8][4], al[2][8][4];
#pragma unroll
    for (int t = 0; t < 2; ++t)
#pragma unroll
    for (int ks = 0; ks < 8; ++ks) {
        LDSM4(ah[t][ks], aHb + t * 16 * ASTRIDE + ks * 32);
        LDSM4(al[t][ks], aLb + t * 16 * ASTRIDE + ks * 32);
    }

#pragma unroll 1
    for (int c = 0; c < 8; ++c) {
        CP_WAIT0();
        __syncthreads();
        if (c + 1 < 8) issueB(sb, tid, mat, c + 1, (c + 1) & 1);
        else if (nextMat >= 0) issueB(sb, tid, nextMat, 0, 0);

        const uint32_t bb = sb + BST_OFF + (c & 1) * (2 * BPART)
                          + rowB * ASTRIDE + koffB;
        uint32_t bH = bb, bL = bb + BPART;

        float acc[2][2][4] = {};

#pragma unroll
        for (int ks = 0; ks < 8; ++ks) {
            uint32_t bh[4], bl[4];
            LDSM4(bh, bH); LDSM4(bl, bL);
            bH += 32; bL += 32;
            MMA(acc[0][0], ah[0][ks], bh[0], bh[1]); MMA(acc[0][1], ah[0][ks], bh[2], bh[3]);
            MMA(acc[1][0], ah[1][ks], bh[0], bh[1]); MMA(acc[1][1], ah[1][ks], bh[2], bh[3]);
            MMA(acc[0][0], al[0][ks], bh[0], bh[1]); MMA(acc[0][1], al[0][ks], bh[2], bh[3]);
            MMA(acc[1][0], al[1][ks], bh[0], bh[1]); MMA(acc[1][1], al[1][ks], bh[2], bh[3]);
            MMA(acc[0][0], ah[0][ks], bl[0], bl[1]); MMA(acc[0][1], ah[0][ks], bl[2], bl[3]);
            MMA(acc[1][0], ah[1][ks], bl[0], bl[1]); MMA(acc[1][1], ah[1][ks], bl[2], bl[3]);
        }

        const int rbase = wm * 32 + gid;
        const int cb = wn * 16 + 2 * tig;
        if (kh) {
#pragma unroll
            for (int t = 0; t < 2; ++t)
#pragma unroll
            for (int u = 0; u < 2; ++u) {
                int r = rbase + t * 16, cc = cb + u * 8;
                *(float2*)&scr[r * 34 + cc]       = make_float2(acc[t][u][0], acc[t][u][1]);
                *(float2*)&scr[(r + 8) * 34 + cc] = make_float2(acc[t][u][2], acc[t][u][3]);
            }
        }
        __syncthreads();
        if (!kh) {
#pragma unroll
            for (int t = 0; t < 2; ++t)
#pragma unroll
            for (int u = 0; u < 2; ++u) {
                int r = rbase + t * 16, cc = cb + u * 8;
                int gcol = c * 32 + cc;
                float2 p0 = *(float2*)&scr[r * 34 + cc];
                float2 p1 = *(float2*)&scr[(r + 8) * 34 + cc];
                float v00 = acc[t][u][0] + p0.x + bias_s[gcol];
                float v01 = acc[t][u][1] + p0.y + bias_s[gcol + 1];
                float v10 = acc[t][u][2] + p1.x + bias_s[gcol];
                float v11 = acc[t][u][3] + p1.y + bias_s[gcol + 1];
                if (do_gelu) {
                    v00 = gelu_f(v00); v01 = gelu_f(v01);
                    v10 = gelu_f(v10); v11 = gelu_f(v11);
                }
                if (toA) {
                    uint32_t lo0, lo1;
                    uint32_t hi0 = pack_hi_lo(v00, v01, &lo0);
                    uint32_t hi1 = pack_hi_lo(v10, v11, &lo1);
                    unsigned char* dh = smem + c_AH[cur ^ 1];
                    unsigned char* dl = smem + c_AL[cur ^ 1];
                    *(uint32_t*)(dh + r * ASTRIDE + gcol * 2) = hi0;
                    *(uint32_t*)(dl + r * ASTRIDE + gcol * 2) = lo0;
                    *(uint32_t*)(dh + (r + 8) * ASTRIDE + gcol * 2) = hi1;
                    *(uint32_t*)(dl + (r + 8) * ASTRIDE + gcol * 2) = lo1;
                } else {
                    float* z0 = g_z + ((size_t)slot * Bq + b0 + r) * 256 + gcol;
                    float* z1 = g_z + ((size_t)slot * Bq + b0 + r + 8) * 256 + gcol;
                    *(float2*)z0 = make_float2(v00, v01);
                    *(float2*)z1 = make_float2(v10, v11);
                }
            }
        }
    }
    __syncthreads();
}

__global__ void __launch_bounds__(256, 1)
mlp_kernel(const float* __restrict__ x,
           const float* __restrict__ Tb1, const float* __restrict__ Tb2,
           const float* __restrict__ Eb1, const float* __restrict__ Eb2)
{
    const uint32_t sb = smem_u32(smem);
    const int tid = threadIdx.x;
    const int b0 = blockIdx.x * 64;

    issueB(sb, tid, 0, 0, 0);   // prefetch chunk0 of first layer

#pragma unroll 1
    for (int br = 0; br < 12; ++br) {
        // load x rows -> A0 (hi/lo split)
        {
            const int row = tid >> 2;
            const int cbase = (tid & 3) * 64;
            const float4* src = (const float4*)(x + (size_t)(b0 + row) * 256 + cbase);
            unsigned char* ah = smem + c_AH[0] + row * ASTRIDE;
            unsigned char* al = smem + c_AL[0] + row * ASTRIDE;
#pragma unroll
            for (int i = 0; i < 16; ++i) {
                float4 v = src[i];
                int col = cbase + i * 4;
                uint32_t l0, l1;
                uint32_t h0 = pack_hi_lo(v.x, v.y, &l0);
                uint32_t h1 = pack_hi_lo(v.z, v.w, &l1);
                *(uint32_t*)(ah + col * 2) = h0;
                *(uint32_t*)(ah + col * 2 + 4) = h1;
                *(uint32_t*)(al + col * 2) = l0;
                *(uint32_t*)(al + col * 2 + 4) = l1;
            }
        }
        __syncthreads();

        int cur = 0;
        if (br < 11) {
            do_layer(sb, tid, cur, br,      11 + br, Tb1 + br * 256, true,  true, 0, b0); cur ^= 1;
            do_layer(sb, tid, cur, 11 + br, 22,      Tb2 + br * 256, false, true, 0, b0); cur ^= 1;
            do_layer(sb, tid, cur, 22,      23,      Eb1, true,  true,  0,  b0); cur ^= 1;
            do_layer(sb, tid, cur, 23, (br + 1 < 11) ? br + 1 : 22, Eb2, false, false, br, b0);
        } else {
            do_layer(sb, tid, cur, 22, 23, Eb1, true,  true,  0,  b0); cur ^= 1;
            do_layer(sb, tid, cur, 23, -1, Eb2, false, false, br, b0);
        }
    }
}

// ---------------- scoring kernel: warp per row ----------------
__global__ void __launch_bounds__(256)
score_kernel(float* __restrict__ out) {
    int lane = threadIdx.x & 31;
    int wid = blockIdx.x * (blockDim.x >> 5) + (threadIdx.x >> 5);
    int nw = gridDim.x * (blockDim.x >> 5);
    for (int row = wid; row < Bq; row += nw) {
        float v[12][8];
#pragma unroll
        for (int s = 0; s < 12; ++s) {
            const float* p = g_z + ((size_t)s * Bq + row) * 256 + lane;
#pragma unroll
            for (int u = 0; u < 8; ++u) v[s][u] = p[u * 32];
        }
        float inrm[12];
#pragma unroll
        for (int s = 0; s < 12; ++s) {
            float d = 0.f;
#pragma unroll
            for (int u = 0; u < 8; ++u) d = fmaf(v[s][u], v[s][u], d);
#pragma unroll
            for (int o = 16; o; o >>= 1) d += __shfl_xor_sync(0xffffffffu, d, o);
            inrm[s] = sqrtf(d);
        }
        float negs[11];
#pragma unroll
        for (int k = 0; k < 11; ++k) negs[k] = 0.f;
#pragma unroll
        for (int l = 0; l < 11; ++l) {
#pragma unroll
            for (int k = l + 1; k < 11; ++k) {
                float d = 0.f;
#pragma unroll
                for (int u = 0; u < 8; ++u) d = fmaf(v[l][u], v[k][u], d);
#pragma unroll
                for (int o = 16; o; o >>= 1) d += __shfl_xor_sync(0xffffffffu, d, o);
                float e = expf(d / fmaxf(inrm[l] * inrm[k], 1e-8f));
                negs[l] += e; negs[k] += e;
            }
        }
        float tot = 0.f;
#pragma unroll
        for (int k = 0; k < 11; ++k) {
            float d = 0.f;
#pragma unroll
            for (int u = 0; u < 8; ++u) d = fmaf(v[11][u], v[k][u], d);
#pragma unroll
            for (int o = 16; o; o >>= 1) d += __shfl_xor_sync(0xffffffffu, d, o);
            float sim = expf(d / fmaxf(inrm[11] * inrm[k], 1e-8f));
            tot += log1pf(negs[k] / sim);
        }
        if (lane == 0) out[row] = tot;
    }
}

// ---------------- launcher ----------------
extern "C" void kernel_launch(void* const* d_in, const int* in_sizes, int n_in,
                              void* d_out, int out_size) {
    const float* x   = (const float*)d_in[0];
    const float* Tw1 = (const float*)d_in[1];
    const float* Tb1 = (const float*)d_in[2];
    const float* Tw2 = (const float*)d_in[3];
    const float* Tb2 = (const float*)d_in[4];
    const float* Ew1 = (const float*)d_in[5];
    const float* Eb1 = (const float*)d_in[6];
    const float* Ew2 = (const float*)d_in[7];
    const float* Eb2 = (const float*)d_in[8];
    float* out = (float*)d_out;

    cudaFuncSetAttribute(mlp_kernel, cudaFuncAttributeMaxDynamicSharedMemorySize, SM_BYTES);

    prep_kernel<<<192, 256>>>(Tw1, Tw2, Ew1, Ew2);
    mlp_kernel<<<Bq / 64, 256, SM_BYTES>>>(x, Tb1, Tb2, Eb1, Eb2);
    score_kernel<<<1024, 256>>>(out);
}

// round 8
// speedup vs baseline: 1.2422x; 1.2422x over previous
#include <cuda_runtime.h>
#include <cuda_fp16.h>
#include <math.h>
#include <stdint.h>

#define Bq 65536

// ---------------- device workspaces (sanctioned __device__ scratch) --------
__device__ __align__(16) unsigned char g_wb[24u * 131072u];   // 3 MB: BT fp16
__device__ float g_z[12ull * Bq * 256ull];                    // z vectors fp32

// ---------------- SMEM layout (bytes) ----------------
// bias f32[256] @0 ; A0h @1024 ; A0l @34816 ; A1h @68608 ; A1l @102400
// B stages @136192 (2 x 16896) ; scratch f32[64][34] @169984 (8704)
#define BIAS_OFF 0
#define BST_OFF 136192
#define SCR_OFF 169984
#define SM_BYTES 178688
#define BPART 16896          // 32*528
#define ASTRIDE 528          // bytes per row (264 fp16)

__constant__ int c_AH[2] = {1024, 68608};
__constant__ int c_AL[2] = {34816, 102400};

// ---------------- helpers ----------------
__device__ __forceinline__ uint32_t smem_u32(const void* p) {
    uint32_t a;
    asm("{ .reg .u64 t; cvta.to.shared.u64 t, %1; cvt.u32.u64 %0, t; }" : "=r"(a) : "l"(p));
    return a;
}

#define LDSM4(r, addr) \
    asm volatile("ldmatrix.sync.aligned.m8n8.x4.shared.b16 {%0,%1,%2,%3}, [%4];" \
        : "=r"((r)[0]), "=r"((r)[1]), "=r"((r)[2]), "=r"((r)[3]) : "r"(addr))

#define MMA(acc, a, bb0, bb1) \
    asm volatile("mma.sync.aligned.m16n8k16.row.col.f32.f16.f16.f32 " \
        "{%0,%1,%2,%3},{%4,%5,%6,%7},{%8,%9},{%0,%1,%2,%3};" \
        : "+f"((acc)[0]), "+f"((acc)[1]), "+f"((acc)[2]), "+f"((acc)[3]) \
        : "r"((a)[0]), "r"((a)[1]), "r"((a)[2]), "r"((a)[3]), "r"(bb0), "r"(bb1))

__device__ __forceinline__ void cpa16(uint32_t dst, const void* src) {
    asm volatile("cp.async.cg.shared.global [%0], [%1], 16;" :: "r"(dst), "l"(src));
}
#define CP_COMMIT() asm volatile("cp.async.commit_group;" ::: "memory")
#define CP_WAIT0()  asm volatile("cp.async.wait_group 0;" ::: "memory")

// pack two floats into fp16x2 hi, and fp16x2 residual lo
__device__ __forceinline__ uint32_t pack_hi_lo(float a, float b, uint32_t* lo) {
    __half ha = __float2half_rn(a), hb = __float2half_rn(b);
    float ra = a - __half2float(ha), rb = b - __half2float(hb);
    __half2 hh = __halves2half2(ha, hb);
    __half2 ll = __halves2half2(__float2half_rn(ra), __float2half_rn(rb));
    *lo = *(uint32_t*)&ll;
    return *(uint32_t*)&hh;
}

__device__ __forceinline__ float gelu_f(float v) {
    return 0.5f * v * (1.0f + erff(v * 0.70710678118654752f));
}

// ---------------- prep: weights -> BT fp16 blobs ----------------
__global__ void prep_kernel(const float* __restrict__ Tw1, const float* __restrict__ Tw2,
                            const float* __restrict__ Ew1, const float* __restrict__ Ew2) {
    int mat = blockIdx.x >> 3, sub = blockIdx.x & 7;
    const float* src = (mat < 11) ? Tw1 + (size_t)mat * 65536
                     : (mat < 22) ? Tw2 + (size_t)(mat - 11) * 65536
                     : (mat == 22) ? Ew1 : Ew2;
    unsigned char* baseH = g_wb + (size_t)mat * 131072u;
    for (int i = 0; i < 32; ++i) {
        int idx = sub * 8192 + i * 256 + threadIdx.x;
        int k = idx >> 8, n = idx & 255;
        __half h = __float2half_rn(src[idx]);
        *(unsigned short*)(baseH + (size_t)n * 512 + (size_t)k * 2) = *(unsigned short*)&h;
    }
}

// ---------------- main fused MLP kernel ----------------
extern __shared__ unsigned char smem[];

__device__ __forceinline__ void issueB(uint32_t sb, int tid, int mat, int c, int stage) {
    const unsigned char* srcbase = g_wb + (size_t)mat * 131072u;
    uint32_t dstbase = sb + BST_OFF + stage * BPART;
#pragma unroll
    for (int i = 0; i < 4; ++i) {
        int g = tid + 256 * i;           // 0..1023
        int rw = g >> 5;                 // row within chunk 0..31
        int u = g & 31;                  // 16B unit within 512B row
        uint32_t dst = dstbase + rw * ASTRIDE + u * 16;
        const unsigned char* s = srcbase + (size_t)(c * 32 + rw) * 512 + (size_t)u * 16;
        cpa16(dst, s);
    }
    CP_COMMIT();
}

__device__ __forceinline__ void do_layer(
    uint32_t sb, int tid, int cur, int mat, int nextMat,
    const float* __restrict__ biasPtr, bool do_gelu, bool toA,
    int slot, int b0)
{
    float* bias_s = (float*)(smem + BIAS_OFF);
    bias_s[tid] = biasPtr[tid];

    const int w = tid >> 5, lane = tid & 31;
    const int kh = w >> 2;              // K half (0: k<128, 1: k>=128)
    const int wm = (w >> 1) & 1;        // 32-row slice
    const int wn = w & 1;               // 16-col slice
    const int gid = lane >> 2, tig = lane & 3;

    const int rowA0 = wm * 32 + (lane & 15);
    const int koffA = (lane >> 4) * 16 + kh * 256;     // bytes
    const int rowB = wn * 16 + ((lane >> 4) << 3) + (lane & 7);
    const int koffB = ((lane >> 3) & 1) * 16 + kh * 256;

    const uint32_t aHb = sb + c_AH[cur] + rowA0 * ASTRIDE + koffA;
    const uint32_t aLb = sb + c_AL[cur] + rowA0 * ASTRIDE + koffA;
    float* scr = (float*)(smem + SCR_OFF);

#pragma unroll 1
    for (int c = 0; c < 8; ++c) {
        CP_WAIT0();
        __syncthreads();
        if (c + 1 < 8) issueB(sb, tid, mat, c + 1, (c + 1) & 1);
        else if (nextMat >= 0) issueB(sb, tid, nextMat, 0, 0);

        uint32_t bB = sb + BST_OFF + (c & 1) * BPART + rowB * ASTRIDE + koffB;
        uint32_t aH = aHb, aL = aLb;

        float acc[2][2][4] = {};

#pragma unroll
        for (int ks = 0; ks < 8; ++ks) {
            uint32_t ah0[4], ah1[4], al0[4], al1[4], bh[4];
            LDSM4(ah0, aH); LDSM4(ah1, aH + 16 * ASTRIDE);
            LDSM4(bh, bB);
            LDSM4(al0, aL); LDSM4(al1, aL + 16 * ASTRIDE);
            aH += 32; aL += 32; bB += 32;
            MMA(acc[0][0], ah0, bh[0], bh[1]); MMA(acc[0][1], ah0, bh[2], bh[3]);
            MMA(acc[1][0], ah1, bh[0], bh[1]); MMA(acc[1][1], ah1, bh[2], bh[3]);
            MMA(acc[0][0], al0, bh[0], bh[1]); MMA(acc[0][1], al0, bh[2], bh[3]);
            MMA(acc[1][0], al1, bh[0], bh[1]); MMA(acc[1][1], al1, bh[2], bh[3]);
        }

        const int rbase = wm * 32 + gid;
        const int cb = wn * 16 + 2 * tig;
        if (kh) {
#pragma unroll
            for (int t = 0; t < 2; ++t)
#pragma unroll
            for (int u = 0; u < 2; ++u) {
                int r = rbase + t * 16, cc = cb + u * 8;
                *(float2*)&scr[r * 34 + cc]       = make_float2(acc[t][u][0], acc[t][u][1]);
                *(float2*)&scr[(r + 8) * 34 + cc] = make_float2(acc[t][u][2], acc[t][u][3]);
            }
        }
        __syncthreads();
        if (!kh) {
#pragma unroll
            for (int t = 0; t < 2; ++t)
#pragma unroll
            for (int u = 0; u < 2; ++u) {
                int r = rbase + t * 16, cc = cb + u * 8;
                int gcol = c * 32 + cc;
                float2 p0 = *(float2*)&scr[r * 34 + cc];
                float2 p1 = *(float2*)&scr[(r + 8) * 34 + cc];
                float v00 = acc[t][u][0] + p0.x + bias_s[gcol];
                float v01 = acc[t][u][1] + p0.y + bias_s[gcol + 1];
                float v10 = acc[t][u][2] + p1.x + bias_s[gcol];
                float v11 = acc[t][u][3] + p1.y + bias_s[gcol + 1];
                if (do_gelu) {
                    v00 = gelu_f(v00); v01 = gelu_f(v01);
                    v10 = gelu_f(v10); v11 = gelu_f(v11);
                }
                if (toA) {
                    uint32_t lo0, lo1;
                    uint32_t hi0 = pack_hi_lo(v00, v01, &lo0);
                    uint32_t hi1 = pack_hi_lo(v10, v11, &lo1);
                    unsigned char* dh = smem + c_AH[cur ^ 1];
                    unsigned char* dl = smem + c_AL[cur ^ 1];
                    *(uint32_t*)(dh + r * ASTRIDE + gcol * 2) = hi0;
                    *(uint32_t*)(dl + r * ASTRIDE + gcol * 2) = lo0;
                    *(uint32_t*)(dh + (r + 8) * ASTRIDE + gcol * 2) = hi1;
                    *(uint32_t*)(dl + (r + 8) * ASTRIDE + gcol * 2) = lo1;
                } else {
                    float* z0 = g_z + ((size_t)slot * Bq + b0 + r) * 256 + gcol;
                    float* z1 = g_z + ((size_t)slot * Bq + b0 + r + 8) * 256 + gcol;
                    *(float2*)z0 = make_float2(v00, v01);
                    *(float2*)z1 = make_float2(v10, v11);
                }
            }
        }
    }
    __syncthreads();
}

__global__ void __launch_bounds__(256, 1)
mlp_kernel(const float* __restrict__ x,
           const float* __restrict__ Tb1, const float* __restrict__ Tb2,
           const float* __restrict__ Eb1, const float* __restrict__ Eb2)
{
    const uint32_t sb = smem_u32(smem);
    const int tid = threadIdx.x;
    const int b0 = blockIdx.x * 64;

    issueB(sb, tid, 0, 0, 0);   // prefetch chunk0 of first layer

#pragma unroll 1
    for (int br = 0; br < 12; ++br) {
        // load x rows -> A0 (hi/lo split)
        {
            const int row = tid >> 2;
            const int cbase = (tid & 3) * 64;
            const float4* src = (const float4*)(x + (size_t)(b0 + row) * 256 + cbase);
            unsigned char* ah = smem + c_AH[0] + row * ASTRIDE;
            unsigned char* al = smem + c_AL[0] + row * ASTRIDE;
#pragma unroll
            for (int i = 0; i < 16; ++i) {
                float4 v = src[i];
                int col = cbase + i * 4;
                uint32_t l0, l1;
                uint32_t h0 = pack_hi_lo(v.x, v.y, &l0);
                uint32_t h1 = pack_hi_lo(v.z, v.w, &l1);
                *(uint32_t*)(ah + col * 2) = h0;
                *(uint32_t*)(ah + col * 2 + 4) = h1;
                *(uint32_t*)(al + col * 2) = l0;
                *(uint32_t*)(al + col * 2 + 4) = l1;
            }
        }
        __syncthreads();

        int cur = 0;
        if (br < 11) {
            do_layer(sb, tid, cur, br,      11 + br, Tb1 + br * 256, true,  true, 0, b0); cur ^= 1;
            do_layer(sb, tid, cur, 11 + br, 22,      Tb2 + br * 256, false, true, 0, b0); cur ^= 1;
            do_layer(sb, tid, cur, 22,      23,      Eb1, true,  true,  0,  b0); cur ^= 1;
            do_layer(sb, tid, cur, 23, (br + 1 < 11) ? br + 1 : 22, Eb2, false, false, br, b0);
        } else {
            do_layer(sb, tid, cur, 22, 23, Eb1, true,  true,  0,  b0); cur ^= 1;
            do_layer(sb, tid, cur, 23, -1, Eb2, false, false, br, b0);
        }
    }
}

// ---------------- scoring kernel: warp per row ----------------
__global__ void __launch_bounds__(256)
score_kernel(float* __restrict__ out) {
    int lane = threadIdx.x & 31;
    int wid = blockIdx.x * (blockDim.x >> 5) + (threadIdx.x >> 5);
    int nw = gridDim.x * (blockDim.x >> 5);
    for (int row = wid; row < Bq; row += nw) {
        float v[12][8];
#pragma unroll
        for (int s = 0; s < 12; ++s) {
            const float* p = g_z + ((size_t)s * Bq + row) * 256 + lane;
#pragma unroll
            for (int u = 0; u < 8; ++u) v[s][u] = p[u * 32];
        }
        float inrm[12];
#pragma unroll
        for (int s = 0; s < 12; ++s) {
            float d = 0.f;
#pragma unroll
            for (int u = 0; u < 8; ++u) d = fmaf(v[s][u], v[s][u], d);
#pragma unroll
            for (int o = 16; o; o >>= 1) d += __shfl_xor_sync(0xffffffffu, d, o);
            inrm[s] = sqrtf(d);
        }
        float negs[11];
#pragma unroll
        for (int k = 0; k < 11; ++k) negs[k] = 0.f;
#pragma unroll
        for (int l = 0; l < 11; ++l) {
#pragma unroll
            for (int k = l + 1; k < 11; ++k) {
                float d = 0.f;
#pragma unroll
                for (int u = 0; u < 8; ++u) d = fmaf(v[l][u], v[k][u], d);
#pragma unroll
                for (int o = 16; o; o >>= 1) d += __shfl_xor_sync(0xffffffffu, d, o);
                float e = expf(d / fmaxf(inrm[l] * inrm[k], 1e-8f));
                negs[l] += e; negs[k] += e;
            }
        }
        float tot = 0.f;
#pragma unroll
        for (int k = 0; k < 11; ++k) {
            float d = 0.f;
#pragma unroll
            for (int u = 0; u < 8; ++u) d = fmaf(v[11][u], v[k][u], d);
#pragma unroll
            for (int o = 16; o; o >>= 1) d += __shfl_xor_sync(0xffffffffu, d, o);
            float sim = expf(d / fmaxf(inrm[11] * inrm[k], 1e-8f));
            tot += log1pf(negs[k] / sim);
        }
        if (lane == 0) out[row] = tot;
    }
}

// ---------------- launcher ----------------
extern "C" void kernel_launch(void* const* d_in, const int* in_sizes, int n_in,
                              void* d_out, int out_size) {
    const float* x   = (const float*)d_in[0];
    const float* Tw1 = (const float*)d_in[1];
    const float* Tb1 = (const float*)d_in[2];
    const float* Tw2 = (const float*)d_in[3];
    const float* Tb2 = (const float*)d_in[4];
    const float* Ew1 = (const float*)d_in[5];
    const float* Eb1 = (const float*)d_in[6];
    const float* Ew2 = (const float*)d_in[7];
    const float* Eb2 = (const float*)d_in[8];
    float* out = (float*)d_out;

    cudaFuncSetAttribute(mlp_kernel, cudaFuncAttributeMaxDynamicSharedMemorySize, SM_BYTES);

    prep_kernel<<<192, 256>>>(Tw1, Tw2, Ew1, Ew2);
    mlp_kernel<<<Bq / 64, 256, SM_BYTES>>>(x, Tb1, Tb2, Eb1, Eb2);
    score_kernel<<<1024, 256>>>(out);
}

// round 9
// speedup vs baseline: 1.7709x; 1.4256x over previous
#include <cuda_runtime.h>
#include <cuda_fp16.h>
#include <math.h>
#include <stdint.h>

#define Bq 65536

// ---------------- device workspaces (sanctioned __device__ scratch) --------
__device__ __align__(16) unsigned char g_wb[24u * 131072u];   // 3 MB: BT fp16
__device__ float g_z[12ull * Bq * 256ull];                    // z vectors fp32

// ---------------- SMEM layout (bytes) ----------------
// bias f32[256] @0 ; A0 @1024 (33792) ; A1 @34816 ;
// B stages @68608 (2 x 16896) ; scratch f32[64][34] @102400 (8704)
#define BIAS_OFF 0
#define BST_OFF 68608
#define SCR_OFF 102400
#define SM_BYTES 111104
#define BPART 16896          // 32*528
#define ASTRIDE 528          // bytes per row (264 fp16)

__constant__ int c_A[2] = {1024, 34816};

// ---------------- helpers ----------------
__device__ __forceinline__ uint32_t smem_u32(const void* p) {
    uint32_t a;
    asm("{ .reg .u64 t; cvta.to.shared.u64 t, %1; cvt.u32.u64 %0, t; }" : "=r"(a) : "l"(p));
    return a;
}

#define LDSM4(r, addr) \
    asm volatile("ldmatrix.sync.aligned.m8n8.x4.shared.b16 {%0,%1,%2,%3}, [%4];" \
        : "=r"((r)[0]), "=r"((r)[1]), "=r"((r)[2]), "=r"((r)[3]) : "r"(addr))

#define MMA(acc, a, bb0, bb1) \
    asm volatile("mma.sync.aligned.m16n8k16.row.col.f32.f16.f16.f32 " \
        "{%0,%1,%2,%3},{%4,%5,%6,%7},{%8,%9},{%0,%1,%2,%3};" \
        : "+f"((acc)[0]), "+f"((acc)[1]), "+f"((acc)[2]), "+f"((acc)[3]) \
        : "r"((a)[0]), "r"((a)[1]), "r"((a)[2]), "r"((a)[3]), "r"(bb0), "r"(bb1))

__device__ __forceinline__ void cpa16(uint32_t dst, const void* src) {
    asm volatile("cp.async.cg.shared.global [%0], [%1], 16;" :: "r"(dst), "l"(src));
}
#define CP_COMMIT() asm volatile("cp.async.commit_group;" ::: "memory")
#define CP_WAIT0()  asm volatile("cp.async.wait_group 0;" ::: "memory")

__device__ __forceinline__ uint32_t pack_h2(float a, float b) {
    __half2 h = __floats2half2_rn(a, b);
    return *(uint32_t*)&h;
}

__device__ __forceinline__ float gelu_f(float v) {
    return 0.5f * v * (1.0f + erff(v * 0.70710678118654752f));
}

// ---------------- prep: weights -> BT fp16 blobs ----------------
__global__ void prep_kernel(const float* __restrict__ Tw1, const float* __restrict__ Tw2,
                            const float* __restrict__ Ew1, const float* __restrict__ Ew2) {
    int mat = blockIdx.x >> 3, sub = blockIdx.x & 7;
    const float* src = (mat < 11) ? Tw1 + (size_t)mat * 65536
                     : (mat < 22) ? Tw2 + (size_t)(mat - 11) * 65536
                     : (mat == 22) ? Ew1 : Ew2;
    unsigned char* baseH = g_wb + (size_t)mat * 131072u;
    for (int i = 0; i < 32; ++i) {
        int idx = sub * 8192 + i * 256 + threadIdx.x;
        int k = idx >> 8, n = idx & 255;
        __half h = __float2half_rn(src[idx]);
        *(unsigned short*)(baseH + (size_t)n * 512 + (size_t)k * 2) = *(unsigned short*)&h;
    }
}

// ---------------- main fused MLP kernel ----------------
extern __shared__ unsigned char smem[];

__device__ __forceinline__ void issueB(uint32_t sb, int tid, int mat, int c, int stage) {
    const unsigned char* srcbase = g_wb + (size_t)mat * 131072u;
    uint32_t dstbase = sb + BST_OFF + stage * BPART;
#pragma unroll
    for (int i = 0; i < 4; ++i) {
        int g = tid + 256 * i;           // 0..1023
        int rw = g >> 5;                 // row within chunk 0..31
        int u = g & 31;                  // 16B unit within 512B row
        uint32_t dst = dstbase + rw * ASTRIDE + u * 16;
        const unsigned char* s = srcbase + (size_t)(c * 32 + rw) * 512 + (size_t)u * 16;
        cpa16(dst, s);
    }
    CP_COMMIT();
}

__device__ __forceinline__ void do_layer(
    uint32_t sb, int tid, int cur, int mat, int nextMat,
    const float* __restrict__ biasPtr, bool do_gelu, bool toA,
    int slot, int b0)
{
    float* bias_s = (float*)(smem + BIAS_OFF);
    bias_s[tid] = biasPtr[tid];

    const int w = tid >> 5, lane = tid & 31;
    const int kh = w >> 2;              // K half (0: k<128, 1: k>=128)
    const int wm = (w >> 1) & 1;        // 32-row slice
    const int wn = w & 1;               // 16-col slice
    const int gid = lane >> 2, tig = lane & 3;

    const int rowA0 = wm * 32 + (lane & 15);
    const int koffA = (lane >> 4) * 16 + kh * 256;     // bytes
    const int rowB = wn * 16 + ((lane >> 4) << 3) + (lane & 7);
    const int koffB = ((lane >> 3) & 1) * 16 + kh * 256;

    const uint32_t aB = sb + c_A[cur] + rowA0 * ASTRIDE + koffA;
    float* scr = (float*)(smem + SCR_OFF);

#pragma unroll 1
    for (int c = 0; c < 8; ++c) {
        CP_WAIT0();
        __syncthreads();
        if (c + 1 < 8) issueB(sb, tid, mat, c + 1, (c + 1) & 1);
        else if (nextMat >= 0) issueB(sb, tid, nextMat, 0, 0);

        uint32_t bB = sb + BST_OFF + (c & 1) * BPART + rowB * ASTRIDE + koffB;
        uint32_t aA = aB;

        float acc[2][2][4] = {};

#pragma unroll
        for (int ks = 0; ks < 8; ++ks) {
            uint32_t a0[4], a1[4], bh[4];
            LDSM4(a0, aA); LDSM4(a1, aA + 16 * ASTRIDE);
            LDSM4(bh, bB);
            aA += 32; bB += 32;
            MMA(acc[0][0], a0, bh[0], bh[1]); MMA(acc[0][1], a0, bh[2], bh[3]);
            MMA(acc[1][0], a1, bh[0], bh[1]); MMA(acc[1][1], a1, bh[2], bh[3]);
        }

        const int rbase = wm * 32 + gid;
        const int cb = wn * 16 + 2 * tig;
        if (kh) {
#pragma unroll
            for (int t = 0; t < 2; ++t)
#pragma unroll
            for (int u = 0; u < 2; ++u) {
                int r = rbase + t * 16, cc = cb + u * 8;
                *(float2*)&scr[r * 34 + cc]       = make_float2(acc[t][u][0], acc[t][u][1]);
                *(float2*)&scr[(r + 8) * 34 + cc] = make_float2(acc[t][u][2], acc[t][u][3]);
            }
        }
        __syncthreads();
        if (!kh) {
#pragma unroll
            for (int t = 0; t < 2; ++t)
#pragma unroll
            for (int u = 0; u < 2; ++u) {
                int r = rbase + t * 16, cc = cb + u * 8;
                int gcol = c * 32 + cc;
                float2 p0 = *(float2*)&scr[r * 34 + cc];
                float2 p1 = *(float2*)&scr[(r + 8) * 34 + cc];
                float v00 = acc[t][u][0] + p0.x + bias_s[gcol];
                float v01 = acc[t][u][1] + p0.y + bias_s[gcol + 1];
                float v10 = acc[t][u][2] + p1.x + bias_s[gcol];
                float v11 = acc[t][u][3] + p1.y + bias_s[gcol + 1];
                if (do_gelu) {
                    v00 = gelu_f(v00); v01 = gelu_f(v01);
                    v10 = gelu_f(v10); v11 = gelu_f(v11);
                }
                if (toA) {
                    unsigned char* da = smem + c_A[cur ^ 1];
                    *(uint32_t*)(da + r * ASTRIDE + gcol * 2) = pack_h2(v00, v01);
                    *(uint32_t*)(da + (r + 8) * ASTRIDE + gcol * 2) = pack_h2(v10, v11);
                } else {
                    float* z0 = g_z + ((size_t)slot * Bq + b0 + r) * 256 + gcol;
                    float* z1 = g_z + ((size_t)slot * Bq + b0 + r + 8) * 256 + gcol;
                    *(float2*)z0 = make_float2(v00, v01);
                    *(float2*)z1 = make_float2(v10, v11);
                }
            }
        }
    }
    __syncthreads();
}

__global__ void __launch_bounds__(256, 2)
mlp_kernel(const float* __restrict__ x,
           const float* __restrict__ Tb1, const float* __restrict__ Tb2,
           const float* __restrict__ Eb1, const float* __restrict__ Eb2)
{
    const uint32_t sb = smem_u32(smem);
    const int tid = threadIdx.x;
    const int b0 = blockIdx.x * 64;

    issueB(sb, tid, 0, 0, 0);   // prefetch chunk0 of first layer

#pragma unroll 1
    for (int br = 0; br < 12; ++br) {
        // load x rows -> A0 (fp16)
        {
            const int row = tid >> 2;
            const int cbase = (tid & 3) * 64;
            const float4* src = (const float4*)(x + (size_t)(b0 + row) * 256 + cbase);
            unsigned char* da = smem + c_A[0] + row * ASTRIDE;
#pragma unroll
            for (int i = 0; i < 16; ++i) {
                float4 v = src[i];
                int col = cbase + i * 4;
                *(uint32_t*)(da + col * 2)     = pack_h2(v.x, v.y);
                *(uint32_t*)(da + col * 2 + 4) = pack_h2(v.z, v.w);
            }
        }
        __syncthreads();

        int cur = 0;
        if (br < 11) {
            do_layer(sb, tid, cur, br,      11 + br, Tb1 + br * 256, true,  true, 0, b0); cur ^= 1;
            do_layer(sb, tid, cur, 11 + br, 22,      Tb2 + br * 256, false, true, 0, b0); cur ^= 1;
            do_layer(sb, tid, cur, 22,      23,      Eb1, true,  true,  0,  b0); cur ^= 1;
            do_layer(sb, tid, cur, 23, (br + 1 < 11) ? br + 1 : 22, Eb2, false, false, br, b0);
        } else {
            do_layer(sb, tid, cur, 22, 23, Eb1, true,  true,  0,  b0); cur ^= 1;
            do_layer(sb, tid, cur, 23, -1, Eb2, false, false, br, b0);
        }
    }
}

// ---------------- scoring kernel: warp per row ----------------
__global__ void __launch_bounds__(256)
score_kernel(float* __restrict__ out) {
    int lane = threadIdx.x & 31;
    int wid = blockIdx.x * (blockDim.x >> 5) + (threadIdx.x >> 5);
    int nw = gridDim.x * (blockDim.x >> 5);
    for (int row = wid; row < Bq; row += nw) {
        float v[12][8];
#pragma unroll
        for (int s = 0; s < 12; ++s) {
            const float* p = g_z + ((size_t)s * Bq + row) * 256 + lane;
#pragma unroll
            for (int u = 0; u < 8; ++u) v[s][u] = p[u * 32];
        }
        float inrm[12];
#pragma unroll
        for (int s = 0; s < 12; ++s) {
            float d = 0.f;
#pragma unroll
            for (int u = 0; u < 8; ++u) d = fmaf(v[s][u], v[s][u], d);
#pragma unroll
            for (int o = 16; o; o >>= 1) d += __shfl_xor_sync(0xffffffffu, d, o);
            inrm[s] = sqrtf(d);
        }
        float negs[11];
#pragma unroll
        for (int k = 0; k < 11; ++k) negs[k] = 0.f;
#pragma unroll
        for (int l = 0; l < 11; ++l) {
#pragma unroll
            for (int k = l + 1; k < 11; ++k) {
                float d = 0.f;
#pragma unroll
                for (int u = 0; u < 8; ++u) d = fmaf(v[l][u], v[k][u], d);
#pragma unroll
                for (int o = 16; o; o >>= 1) d += __shfl_xor_sync(0xffffffffu, d, o);
                float e = expf(d / fmaxf(inrm[l] * inrm[k], 1e-8f));
                negs[l] += e; negs[k] += e;
            }
        }
        float tot = 0.f;
#pragma unroll
        for (int k = 0; k < 11; ++k) {
            float d = 0.f;
#pragma unroll
            for (int u = 0; u < 8; ++u) d = fmaf(v[11][u], v[k][u], d);
#pragma unroll
            for (int o = 16; o; o >>= 1) d += __shfl_xor_sync(0xffffffffu, d, o);
            float sim = expf(d / fmaxf(inrm[11] * inrm[k], 1e-8f));
            tot += log1pf(negs[k] / sim);
        }
        if (lane == 0) out[row] = tot;
    }
}

// ---------------- launcher ----------------
extern "C" void kernel_launch(void* const* d_in, const int* in_sizes, int n_in,
                              void* d_out, int out_size) {
    const float* x   = (const float*)d_in[0];
    const float* Tw1 = (const float*)d_in[1];
    const float* Tb1 = (const float*)d_in[2];
    const float* Tw2 = (const float*)d_in[3];
    const float* Tb2 = (const float*)d_in[4];
    const float* Ew1 = (const float*)d_in[5];
    const float* Eb1 = (const float*)d_in[6];
    const float* Ew2 = (const float*)d_in[7];
    const float* Eb2 = (const float*)d_in[8];
    float* out = (float*)d_out;

    cudaFuncSetAttribute(mlp_kernel, cudaFuncAttributeMaxDynamicSharedMemorySize, SM_BYTES);

    prep_kernel<<<192, 256>>>(Tw1, Tw2, Ew1, Ew2);
    mlp_kernel<<<Bq / 64, 256, SM_BYTES>>>(x, Tb1, Tb2, Eb1, Eb2);
    score_kernel<<<1024, 256>>>(out);
}

// round 11
// speedup vs baseline: 1.8420x; 1.0401x over previous
#include <cuda_runtime.h>
#include <cuda_fp16.h>
#include <math.h>
#include <stdint.h>

#define Bq 65536

// ---------------- device workspaces (sanctioned __device__ scratch) --------
__device__ __align__(16) unsigned char g_wb[24u * 131072u];   // 3 MB: BT fp16
__device__ float g_z[12ull * Bq * 256ull];                    // z vectors fp32

// ---------------- SMEM layout (bytes) ----------------
#define BIAS_OFF 0
#define BST_OFF 68608
#define SCR_OFF 102400
#define SM_BYTES 111104
#define BPART 16896          // 32*528
#define ASTRIDE 528          // bytes per row (264 fp16)

__constant__ int c_A[2] = {1024, 34816};

// ---------------- helpers ----------------
__device__ __forceinline__ uint32_t smem_u32(const void* p) {
    uint32_t a;
    asm("{ .reg .u64 t; cvta.to.shared.u64 t, %1; cvt.u32.u64 %0, t; }" : "=r"(a) : "l"(p));
    return a;
}

#define LDSM4(r, addr) \
    asm volatile("ldmatrix.sync.aligned.m8n8.x4.shared.b16 {%0,%1,%2,%3}, [%4];" \
        : "=r"((r)[0]), "=r"((r)[1]), "=r"((r)[2]), "=r"((r)[3]) : "r"(addr))

#define MMA(acc, a, bb0, bb1) \
    asm volatile("mma.sync.aligned.m16n8k16.row.col.f32.f16.f16.f32 " \
        "{%0,%1,%2,%3},{%4,%5,%6,%7},{%8,%9},{%0,%1,%2,%3};" \
        : "+f"((acc)[0]), "+f"((acc)[1]), "+f"((acc)[2]), "+f"((acc)[3]) \
        : "r"((a)[0]), "r"((a)[1]), "r"((a)[2]), "r"((a)[3]), "r"(bb0), "r"(bb1))

__device__ __forceinline__ void cpa16(uint32_t dst, const void* src) {
    asm volatile("cp.async.cg.shared.global [%0], [%1], 16;" :: "r"(dst), "l"(src));
}
#define CP_COMMIT() asm volatile("cp.async.commit_group;" ::: "memory")
#define CP_WAIT0()  asm volatile("cp.async.wait_group 0;" ::: "memory")

__device__ __forceinline__ uint32_t pack_h2(float a, float b) {
    __half2 h = __floats2half2_rn(a, b);
    return *(uint32_t*)&h;
}

__device__ __forceinline__ float gelu_f(float v) {
    return 0.5f * v * (1.0f + erff(v * 0.70710678118654752f));
}

// ---------------- prep: weights -> BT fp16 blobs ----------------
__global__ void prep_kernel(const float* __restrict__ Tw1, const float* __restrict__ Tw2,
                            const float* __restrict__ Ew1, const float* __restrict__ Ew2) {
    int mat = blockIdx.x >> 3, sub = blockIdx.x & 7;
    const float* src = (mat < 11) ? Tw1 + (size_t)mat * 65536
                     : (mat < 22) ? Tw2 + (size_t)(mat - 11) * 65536
                     : (mat == 22) ? Ew1 : Ew2;
    unsigned char* baseH = g_wb + (size_t)mat * 131072u;
    for (int i = 0; i < 32; ++i) {
        int idx = sub * 8192 + i * 256 + threadIdx.x;
        int k = idx >> 8, n = idx & 255;
        __half h = __float2half_rn(src[idx]);
        *(unsigned short*)(baseH + (size_t)n * 512 + (size_t)k * 2) = *(unsigned short*)&h;
    }
}

// ---------------- main fused MLP kernel ----------------
extern __shared__ unsigned char smem[];

__device__ __forceinline__ void issueB(uint32_t sb, int tid, int mat, int c, int stage) {
    const unsigned char* srcbase = g_wb + (size_t)mat * 131072u;
    uint32_t dstbase = sb + BST_OFF + stage * BPART;
#pragma unroll
    for (int i = 0; i < 4; ++i) {
        int g = tid + 256 * i;           // 0..1023
        int rw = g >> 5;                 // row within chunk 0..31
        int u = g & 31;                  // 16B unit within 512B row
        uint32_t dst = dstbase + rw * ASTRIDE + u * 16;
        const unsigned char* s = srcbase + (size_t)(c * 32 + rw) * 512 + (size_t)u * 16;
        cpa16(dst, s);
    }
    CP_COMMIT();
}

__device__ __forceinline__ void do_layer(
    uint32_t sb, int tid, int cur, int mat, int nextMat,
    const float* __restrict__ biasPtr, bool do_gelu, bool toA,
    int slot, int b0)
{
    float* bias_s = (float*)(smem + BIAS_OFF);
    bias_s[tid] = biasPtr[tid];

    const int w = tid >> 5, lane = tid & 31;
    const int kh = w >> 2;              // K half (0: k<128, 1: k>=128)
    const int wm = (w >> 1) & 1;        // 32-row slice
    const int wn = w & 1;               // 16-col slice
    const int gid = lane >> 2, tig = lane & 3;

    const int rowA0 = wm * 32 + (lane & 15);
    const int koffA = (lane >> 4) * 16 + kh * 256;     // bytes
    const int rowB = wn * 16 + ((lane >> 4) << 3) + (lane & 7);
    const int koffB = ((lane >> 3) & 1) * 16 + kh * 256;

    const uint32_t aB = sb + c_A[cur] + rowA0 * ASTRIDE + koffA;
    float* scr = (float*)(smem + SCR_OFF);

    // ---- A-stationary: preload this warp's A slice (32 rows x 128 k fp16) ----
    uint32_t areg[2][8][4];
#pragma unroll
    for (int t = 0; t < 2; ++t)
#pragma unroll
    for (int ks = 0; ks < 8; ++ks)
        LDSM4(areg[t][ks], aB + t * 16 * ASTRIDE + ks * 32);

#pragma unroll 1
    for (int c = 0; c < 8; ++c) {
        CP_WAIT0();
        __syncthreads();
        if (c + 1 < 8) issueB(sb, tid, mat, c + 1, (c + 1) & 1);
        else if (nextMat >= 0) issueB(sb, tid, nextMat, 0, 0);

        uint32_t bB = sb + BST_OFF + (c & 1) * BPART + rowB * ASTRIDE + koffB;

        float acc[2][2][4] = {};

#pragma unroll
        for (int ks = 0; ks < 8; ++ks) {
            uint32_t bh[4];
            LDSM4(bh, bB);
            bB += 32;
            MMA(acc[0][0], areg[0][ks], bh[0], bh[1]); MMA(acc[0][1], areg[0][ks], bh[2], bh[3]);
            MMA(acc[1][0], areg[1][ks], bh[0], bh[1]); MMA(acc[1][1], areg[1][ks], bh[2], bh[3]);
        }

        const int rbase = wm * 32 + gid;
        const int cb = wn * 16 + 2 * tig;
        if (kh) {
#pragma unroll
            for (int t = 0; t < 2; ++t)
#pragma unroll
            for (int u = 0; u < 2; ++u) {
                int r = rbase + t * 16, cc = cb + u * 8;
                *(float2*)&scr[r * 34 + cc]       = make_float2(acc[t][u][0], acc[t][u][1]);
                *(float2*)&scr[(r + 8) * 34 + cc] = make_float2(acc[t][u][2], acc[t][u][3]);
            }
        }
        __syncthreads();
        if (!kh) {
#pragma unroll
            for (int t = 0; t < 2; ++t)
#pragma unroll
            for (int u = 0; u < 2; ++u) {
                int r = rbase + t * 16, cc = cb + u * 8;
                int gcol = c * 32 + cc;
                float2 p0 = *(float2*)&scr[r * 34 + cc];
                float2 p1 = *(float2*)&scr[(r + 8) * 34 + cc];
                float v00 = acc[t][u][0] + p0.x + bias_s[gcol];
                float v01 = acc[t][u][1] + p0.y + bias_s[gcol + 1];
                float v10 = acc[t][u][2] + p1.x + bias_s[gcol];
                float v11 = acc[t][u][3] + p1.y + bias_s[gcol + 1];
                if (do_gelu) {
                    v00 = gelu_f(v00); v01 = gelu_f(v01);
                    v10 = gelu_f(v10); v11 = gelu_f(v11);
                }
                if (toA) {
                    unsigned char* da = smem + c_A[cur ^ 1];
                    *(uint32_t*)(da + r * ASTRIDE + gcol * 2) = pack_h2(v00, v01);
                    *(uint32_t*)(da + (r + 8) * ASTRIDE + gcol * 2) = pack_h2(v10, v11);
                } else {
                    float* z0 = g_z + ((size_t)slot * Bq + b0 + r) * 256 + gcol;
                    float* z1 = g_z + ((size_t)slot * Bq + b0 + r + 8) * 256 + gcol;
                    *(float2*)z0 = make_float2(v00, v01);
                    *(float2*)z1 = make_float2(v10, v11);
                }
            }
        }
    }
    __syncthreads();
}

__global__ void __launch_bounds__(256, 2)
mlp_kernel(const float* __restrict__ x,
           const float* __restrict__ Tb1, const float* __restrict__ Tb2,
           const float* __restrict__ Eb1, const float* __restrict__ Eb2)
{
    const uint32_t sb = smem_u32(smem);
    const int tid = threadIdx.x;
    const int b0 = blockIdx.x * 64;

    issueB(sb, tid, 0, 0, 0);   // prefetch chunk0 of first layer

#pragma unroll 1
    for (int br = 0; br < 12; ++br) {
        // load x rows -> A0 (fp16)
        {
            const int row = tid >> 2;
            const int cbase = (tid & 3) * 64;
            const float4* src = (const float4*)(x + (size_t)(b0 + row) * 256 + cbase);
            unsigned char* da = smem + c_A[0] + row * ASTRIDE;
#pragma unroll
            for (int i = 0; i < 16; ++i) {
                float4 v = src[i];
                int col = cbase + i * 4;
                *(uint32_t*)(da + col * 2)     = pack_h2(v.x, v.y);
                *(uint32_t*)(da + col * 2 + 4) = pack_h2(v.z, v.w);
            }
        }
        __syncthreads();

        int cur = 0;
        if (br < 11) {
            do_layer(sb, tid, cur, br,      11 + br, Tb1 + br * 256, true,  true, 0, b0); cur ^= 1;
            do_layer(sb, tid, cur, 11 + br, 22,      Tb2 + br * 256, false, true, 0, b0); cur ^= 1;
            do_layer(sb, tid, cur, 22,      23,      Eb1, true,  true,  0,  b0); cur ^= 1;
            do_layer(sb, tid, cur, 23, (br + 1 < 11) ? br + 1 : 22, Eb2, false, false, br, b0);
        } else {
            do_layer(sb, tid, cur, 22, 23, Eb1, true,  true,  0,  b0); cur ^= 1;
            do_layer(sb, tid, cur, 23, -1, Eb2, false, false, br, b0);
        }
    }
}

// ---------------- scoring kernel: warp per row ----------------
__global__ void __launch_bounds__(256)
score_kernel(float* __restrict__ out) {
    int lane = threadIdx.x & 31;
    int wid = blockIdx.x * (blockDim.x >> 5) + (threadIdx.x >> 5);
    int nw = gridDim.x * (blockDim.x >> 5);
    for (int row = wid; row < Bq; row += nw) {
        float v[12][8];
#pragma unroll
        for (int s = 0; s < 12; ++s) {
            const float* p = g_z + ((size_t)s * Bq + row) * 256 + lane;
#pragma unroll
            for (int u = 0; u < 8; ++u) v[s][u] = p[u * 32];
        }
        float inrm[12];
#pragma unroll
        for (int s = 0; s < 12; ++s) {
            float d = 0.f;
#pragma unroll
            for (int u = 0; u < 8; ++u) d = fmaf(v[s][u], v[s][u], d);
#pragma unroll
            for (int o = 16; o; o >>= 1) d += __shfl_xor_sync(0xffffffffu, d, o);
            inrm[s] = sqrtf(d);
        }
        float negs[11];
#pragma unroll
        for (int k = 0; k < 11; ++k) negs[k] = 0.f;
#pragma unroll
        for (int l = 0; l < 11; ++l) {
#pragma unroll
            for (int k = l + 1; k < 11; ++k) {
                float d = 0.f;
#pragma unroll
                for (int u = 0; u < 8; ++u) d = fmaf(v[l][u], v[k][u], d);
#pragma unroll
                for (int o = 16; o; o >>= 1) d += __shfl_xor_sync(0xffffffffu, d, o);
                float e = expf(d / fmaxf(inrm[l] * inrm[k], 1e-8f));
                negs[l] += e; negs[k] += e;
            }
        }
        float tot = 0.f;
#pragma unroll
        for (int k = 0; k < 11; ++k) {
            float d = 0.f;
#pragma unroll
            for (int u = 0; u < 8; ++u) d = fmaf(v[11][u], v[k][u], d);
#pragma unroll
            for (int o = 16; o; o >>= 1) d += __shfl_xor_sync(0xffffffffu, d, o);
            float sim = expf(d / fmaxf(inrm[11] * inrm[k], 1e-8f));
            tot += log1pf(negs[k] / sim);
        }
        if (lane == 0) out[row] = tot;
    }
}

// ---------------- launcher ----------------
extern "C" void kernel_launch(void* const* d_in, const int* in_sizes, int n_in,
                              void* d_out, int out_size) {
    const float* x   = (const float*)d_in[0];
    const float* Tw1 = (const float*)d_in[1];
    const float* Tb1 = (const float*)d_in[2];
    const float* Tw2 = (const float*)d_in[3];
    const float* Tb2 = (const float*)d_in[4];
    const float* Ew1 = (const float*)d_in[5];
    const float* Eb1 = (const float*)d_in[6];
    const float* Ew2 = (const float*)d_in[7];
    const float* Eb2 = (const float*)d_in[8];
    float* out = (float*)d_out;

    cudaFuncSetAttribute(mlp_kernel, cudaFuncAttributeMaxDynamicSharedMemorySize, SM_BYTES);

    prep_kernel<<<192, 256>>>(Tw1, Tw2, Ew1, Ew2);
    mlp_kernel<<<Bq / 64, 256, SM_BYTES>>>(x, Tb1, Tb2, Eb1, Eb2);
    score_kernel<<<1024, 256>>>(out);
}